// round 1
// baseline (speedup 1.0000x reference)
#include <cuda_runtime.h>

// cost = 0.5 * sum_n x_n^T C_n x_n
// N_BLOCKS = 8192, BLOCK = 64
// d_in[0] = x        [524288] fp32
// d_in[1] = C_blocks [8192*64*64] fp32
// d_out   = [1] fp32

#define N_BLOCKS 8192
#define BLK 64

__device__ double g_acc;

__global__ void zero_kernel() {
    g_acc = 0.0;
}

__global__ __launch_bounds__(256, 4) void quadform_kernel(
    const float* __restrict__ x,
    const float* __restrict__ C)
{
    __shared__ float xs[BLK];
    __shared__ float warp_sums[8];

    const int n = blockIdx.x;          // block index 0..8191
    const int t = threadIdx.x;         // 0..255

    // Stage x block into shared (64 floats; 16 threads x float4)
    if (t < 16) {
        const float4 v = reinterpret_cast<const float4*>(x + n * BLK)[t];
        reinterpret_cast<float4*>(xs)[t] = v;
    }
    __syncthreads();

    // Thread t handles row r = t>>2, columns [q*16, q*16+16), q = t&3.
    const int r = t >> 2;
    const int q = t & 3;
    const float xr = xs[r];

    const float4* Crow = reinterpret_cast<const float4*>(C + (size_t)n * (BLK * BLK) + r * BLK + q * 16);

    // 4 independent float4 loads -> MLP 4 within the thread.
    float4 c0 = Crow[0];
    float4 c1 = Crow[1];
    float4 c2 = Crow[2];
    float4 c3 = Crow[3];

    const int cb = q * 16;
    float inner = 0.f;
    inner += c0.x * xs[cb + 0] + c0.y * xs[cb + 1] + c0.z * xs[cb + 2] + c0.w * xs[cb + 3];
    inner += c1.x * xs[cb + 4] + c1.y * xs[cb + 5] + c1.z * xs[cb + 6] + c1.w * xs[cb + 7];
    inner += c2.x * xs[cb + 8] + c2.y * xs[cb + 9] + c2.z * xs[cb + 10] + c2.w * xs[cb + 11];
    inner += c3.x * xs[cb + 12] + c3.y * xs[cb + 13] + c3.z * xs[cb + 14] + c3.w * xs[cb + 15];

    float acc = xr * inner;

    // Warp reduction
    #pragma unroll
    for (int off = 16; off > 0; off >>= 1)
        acc += __shfl_down_sync(0xFFFFFFFFu, acc, off);

    const int lane = t & 31;
    const int wid  = t >> 5;
    if (lane == 0) warp_sums[wid] = acc;
    __syncthreads();

    if (wid == 0) {
        float s = (lane < 8) ? warp_sums[lane] : 0.f;
        #pragma unroll
        for (int off = 4; off > 0; off >>= 1)
            s += __shfl_down_sync(0xFFFFFFFFu, s, off);
        if (lane == 0)
            atomicAdd(&g_acc, (double)s);
    }
}

__global__ void finalize_kernel(float* __restrict__ out) {
    out[0] = (float)(0.5 * g_acc);
}

extern "C" void kernel_launch(void* const* d_in, const int* in_sizes, int n_in,
                              void* d_out, int out_size) {
    const float* x = (const float*)d_in[0];
    const float* C = (const float*)d_in[1];
    float* out = (float*)d_out;

    zero_kernel<<<1, 1>>>();
    quadform_kernel<<<N_BLOCKS, 256>>>(x, C);
    finalize_kernel<<<1, 1>>>(out);
}

// round 2
// speedup vs baseline: 1.1867x; 1.1867x over previous
#include <cuda_runtime.h>

// cost = 0.5 * sum_n x_n^T C_n x_n
// N_BLOCKS = 8192, BLOCK = 64
// d_in[0] = x        [524288] fp32
// d_in[1] = C_blocks [8192*64*64] fp32
// d_out   = [1] fp32

#define N_BLOCKS 8192
#define BLK 64
#define GRID 1024          // one full wave: <= 148 SMs * 8 CTAs
#define BLOCKS_PER_CTA (N_BLOCKS / GRID)   // 8

__device__ double g_acc;            // zero-initialized at module load
__device__ unsigned int g_count;    // zero-initialized

__global__ __launch_bounds__(256, 8) void quadform_kernel(
    const float* __restrict__ x,
    const float* __restrict__ C,
    float* __restrict__ out)
{
    __shared__ float xs[BLK];
    __shared__ float warp_sums[8];

    const int t    = threadIdx.x;      // 0..255
    const int lane = t & 31;
    const int wid  = t >> 5;

    float acc = 0.f;

    const int n0 = blockIdx.x * BLOCKS_PER_CTA;

    #pragma unroll 1
    for (int i = 0; i < BLOCKS_PER_CTA; i++) {
        const int n = n0 + i;

        // Stage x block into shared (64 floats; 16 threads x float4)
        if (t < 16) {
            reinterpret_cast<float4*>(xs)[t] =
                reinterpret_cast<const float4*>(x + n * BLK)[t];
        }
        __syncthreads();

        // 16 KB of C for this block: 1024 float4s, 4 passes of 256 threads.
        // Pass p: flat float4 index fp = p*256 + t -> warp spans contiguous 512B.
        const float4* C4 = reinterpret_cast<const float4*>(C) + (size_t)n * (BLK * BLK / 4);

        // Issue all 4 independent loads first (MLP = 4).
        float4 v0 = C4[0 * 256 + t];
        float4 v1 = C4[1 * 256 + t];
        float4 v2 = C4[2 * 256 + t];
        float4 v3 = C4[3 * 256 + t];

        const float4* xs4 = reinterpret_cast<const float4*>(xs);

        {   // pass 0: fp = t, row = fp>>4, col4 = fp&15
            const int fp = 0 * 256 + t;
            const float4 xc = xs4[fp & 15];
            acc += xs[fp >> 4] * (v0.x * xc.x + v0.y * xc.y + v0.z * xc.z + v0.w * xc.w);
        }
        {
            const int fp = 1 * 256 + t;
            const float4 xc = xs4[fp & 15];
            acc += xs[fp >> 4] * (v1.x * xc.x + v1.y * xc.y + v1.z * xc.z + v1.w * xc.w);
        }
        {
            const int fp = 2 * 256 + t;
            const float4 xc = xs4[fp & 15];
            acc += xs[fp >> 4] * (v2.x * xc.x + v2.y * xc.y + v2.z * xc.z + v2.w * xc.w);
        }
        {
            const int fp = 3 * 256 + t;
            const float4 xc = xs4[fp & 15];
            acc += xs[fp >> 4] * (v3.x * xc.x + v3.y * xc.y + v3.z * xc.z + v3.w * xc.w);
        }

        __syncthreads();   // before xs is overwritten next iteration
    }

    // Intra-CTA reduction
    #pragma unroll
    for (int off = 16; off > 0; off >>= 1)
        acc += __shfl_down_sync(0xFFFFFFFFu, acc, off);
    if (lane == 0) warp_sums[wid] = acc;
    __syncthreads();

    if (wid == 0) {
        float s = (lane < 8) ? warp_sums[lane] : 0.f;
        #pragma unroll
        for (int off = 4; off > 0; off >>= 1)
            s += __shfl_down_sync(0xFFFFFFFFu, s, off);

        if (lane == 0) {
            atomicAdd(&g_acc, (double)s);
            __threadfence();
            unsigned int done = atomicAdd(&g_count, 1u);
            if (done == GRID - 1) {
                // Last CTA: read the full sum, write output, reset for next replay.
                double total = atomicAdd(&g_acc, 0.0);   // coherent L2 read
                out[0] = (float)(0.5 * total);
                g_acc = 0.0;
                g_count = 0u;
                __threadfence();
            }
        }
    }
}

extern "C" void kernel_launch(void* const* d_in, const int* in_sizes, int n_in,
                              void* d_out, int out_size) {
    const float* x = (const float*)d_in[0];
    const float* C = (const float*)d_in[1];
    float* out = (float*)d_out;

    quadform_kernel<<<GRID, 256>>>(x, C, out);
}

// round 3
// speedup vs baseline: 1.3002x; 1.0957x over previous
#include <cuda_runtime.h>

// cost = 0.5 * sum_n x_n^T C_n x_n
// N_BLOCKS = 8192, BLOCK = 64
// d_in[0] = x        [524288] fp32
// d_in[1] = C_blocks [8192*64*64] fp32
// d_out   = [1] fp32

#define N_BLOCKS 8192
#define BLK 64
#define GRID 1184            // 148 SMs * 8 resident CTAs -> one balanced wave
#define MAXB 7               // ceil(8192 / 1184)

__device__ double g_acc;            // zero-initialized at module load
__device__ unsigned int g_count;    // zero-initialized

__global__ __launch_bounds__(256, 8) void quadform_kernel(
    const float* __restrict__ x,
    const float* __restrict__ C,
    float* __restrict__ out)
{
    __shared__ float xs[MAXB * BLK];   // x slices for all blocks this CTA owns
    __shared__ float warp_sums[8];

    const int t    = threadIdx.x;      // 0..255
    const int lane = t & 31;
    const int wid  = t >> 5;
    const int bid  = blockIdx.x;

    // Preload x for all of this CTA's blocks (grid-stride assignment),
    // then ONE barrier. Main loop below has no barriers at all.
    for (int idx = t; idx < MAXB * 16; idx += 256) {
        const int k = idx >> 4;              // block slot 0..6
        const int n = bid + k * GRID;
        if (n < N_BLOCKS) {
            reinterpret_cast<float4*>(xs)[idx] =
                reinterpret_cast<const float4*>(x)[n * 16 + (idx & 15)];
        }
    }
    __syncthreads();

    float acc = 0.f;

    #pragma unroll 1
    for (int k = 0, n = bid; n < N_BLOCKS; k++, n += GRID) {
        const float4* C4 = reinterpret_cast<const float4*>(C) + (size_t)n * (BLK * BLK / 4);

        // 4 independent, fully coalesced 512B-per-warp loads (MLP >= 4/thread;
        // with no barriers, loads also pipeline across k iterations and warps).
        float4 v0 = C4[0 * 256 + t];
        float4 v1 = C4[1 * 256 + t];
        float4 v2 = C4[2 * 256 + t];
        float4 v3 = C4[3 * 256 + t];

        const float*  xb  = xs + k * BLK;
        const float4* xb4 = reinterpret_cast<const float4*>(xb);

        {   const int fp = 0 * 256 + t;
            const float4 xc = xb4[fp & 15];
            acc += xb[fp >> 4] * (v0.x * xc.x + v0.y * xc.y + v0.z * xc.z + v0.w * xc.w);
        }
        {   const int fp = 1 * 256 + t;
            const float4 xc = xb4[fp & 15];
            acc += xb[fp >> 4] * (v1.x * xc.x + v1.y * xc.y + v1.z * xc.z + v1.w * xc.w);
        }
        {   const int fp = 2 * 256 + t;
            const float4 xc = xb4[fp & 15];
            acc += xb[fp >> 4] * (v2.x * xc.x + v2.y * xc.y + v2.z * xc.z + v2.w * xc.w);
        }
        {   const int fp = 3 * 256 + t;
            const float4 xc = xb4[fp & 15];
            acc += xb[fp >> 4] * (v3.x * xc.x + v3.y * xc.y + v3.z * xc.z + v3.w * xc.w);
        }
    }

    // Intra-CTA reduction
    #pragma unroll
    for (int off = 16; off > 0; off >>= 1)
        acc += __shfl_down_sync(0xFFFFFFFFu, acc, off);
    if (lane == 0) warp_sums[wid] = acc;
    __syncthreads();

    if (wid == 0) {
        float s = (lane < 8) ? warp_sums[lane] : 0.f;
        #pragma unroll
        for (int off = 4; off > 0; off >>= 1)
            s += __shfl_down_sync(0xFFFFFFFFu, s, off);

        if (lane == 0) {
            atomicAdd(&g_acc, (double)s);
            __threadfence();
            unsigned int done = atomicAdd(&g_count, 1u);
            if (done == GRID - 1) {
                // Last CTA: read full sum, write output, reset for next replay.
                double total = atomicAdd(&g_acc, 0.0);
                out[0] = (float)(0.5 * total);
                g_acc = 0.0;
                g_count = 0u;
                __threadfence();
            }
        }
    }
}

extern "C" void kernel_launch(void* const* d_in, const int* in_sizes, int n_in,
                              void* d_out, int out_size) {
    const float* x = (const float*)d_in[0];
    const float* C = (const float*)d_in[1];
    float* out = (float*)d_out;

    quadform_kernel<<<GRID, 256>>>(x, C, out);
}